// round 12
// baseline (speedup 1.0000x reference)
#include <cuda_runtime.h>
#include <stdint.h>

// embeddings: [B=32, L=4, W=512, D=768] f32; segment_ids: [B=32, W=512] i32 sorted/row.
// Out (f32, concat): word [B, D, W] then sent [B, D].
//
// word[b,d,s] = (1/L) * sum_{w: seg[b,w]==s} sum_l emb[b,l,w,d]
// sent[b,d]   = (1/W) * sum_s word[b,d,s]
//
// R11: depth-2 software pipeline (two register pair-sets, 16 LDG.128 in
// flight per thread) + TILE_S=32 (2x main-loop length per block, prologue
// amortized). Barrier-free main loop (thread-owned tile_s columns) kept
// from R10.

#define BB 32
#define LL 4
#define WW 512
#define DD 768

#define TILE_S 32          // segments per block
#define NTHR   96          // threads per block
#define TILE_D (NTHR * 4)  // 384 d-channels per block (float4/thread)
#define TS_ST  388         // tile_s row stride (floats)

__global__ void zero_sent_kernel(float* __restrict__ sent) {
    int i = blockIdx.x * blockDim.x + threadIdx.x;
    if (i < BB * DD) sent[i] = 0.0f;
}

__device__ __forceinline__ float4 sum4(float4 a, float4 b, float4 c, float4 d) {
    float4 r;
    r.x = (a.x + b.x) + (c.x + d.x);
    r.y = (a.y + b.y) + (c.y + d.y);
    r.z = (a.z + b.z) + (c.z + d.z);
    r.w = (a.w + b.w) + (c.w + d.w);
    return r;
}

__global__ __launch_bounds__(NTHR)
void word_agg_kernel(const float* __restrict__ emb,
                     const int*   __restrict__ seg,
                     float*       __restrict__ word,   // [B, D, W]
                     float*       __restrict__ sent)   // [B, D]
{
    __shared__ float tile_s[TILE_S][TS_ST];   // 32 x 388 x 4B = 49,664 B
    __shared__ int   segs[WW];                // 2,048 B

    const int b    = blockIdx.z;
    const int s0   = blockIdx.y * TILE_S;
    const int d0   = blockIdx.x * TILE_D;
    const int tid  = threadIdx.x;
    const int lane = tid & 31;

    #pragma unroll
    for (int i = tid; i < WW; i += NTHR) segs[i] = seg[b * WW + i];

    // Zero tile_s (empty segments must output 0).
    {
        float4* t4 = (float4*)&tile_s[0][0];
        const int n4 = TILE_S * (TS_ST / 4);
        const float4 z = make_float4(0.f, 0.f, 0.f, 0.f);
        for (int i = tid; i < n4; i += NTHR) t4[i] = z;
    }
    __syncthreads();   // segs + zeros visible

    // Per-warp boundary scan: unique i with segs[i-1] < bound <= segs[i].
    int wlo = WW, whi = WW;
    #pragma unroll
    for (int i = lane; i < WW; i += 32) {
        const int v    = segs[i];
        const int prev = (i == 0) ? -1 : segs[i - 1];
        if (prev < s0          && v >= s0)          wlo = i;
        if (prev < s0 + TILE_S && v >= s0 + TILE_S) whi = i;
    }
    wlo = __reduce_min_sync(0xffffffffu, wlo);
    whi = __reduce_min_sync(0xffffffffu, whi);

    const float* __restrict__ base = emb + ((size_t)b * LL * WW) * DD + d0 + tid * 4;
    const size_t LSTRIDE = (size_t)WW * DD;

    // RMW accumulate into the thread-owned tile_s column (no atomics needed).
    auto rmw = [&](int widx, float4 v) {
        float4* row = (float4*)&tile_s[segs[widx] - s0][0];
        float4 t = row[tid];
        t.x += v.x; t.y += v.y; t.z += v.z; t.w += v.w;
        row[tid] = t;
    };
    auto ldpair = [&](int widx, float4* r) {
        const float* p0 = base + (size_t)widx * DD;
        const float* p1 = p0 + DD;
        r[0] = *(const float4*)(p0);
        r[1] = *(const float4*)(p0 + LSTRIDE);
        r[2] = *(const float4*)(p0 + 2 * LSTRIDE);
        r[3] = *(const float4*)(p0 + 3 * LSTRIDE);
        r[4] = *(const float4*)(p1);
        r[5] = *(const float4*)(p1 + LSTRIDE);
        r[6] = *(const float4*)(p1 + 2 * LSTRIDE);
        r[7] = *(const float4*)(p1 + 3 * LSTRIDE);
    };

    int w = wlo;
    if (w + 3 < whi) {
        // Depth-2 prologue: pairs A=(w,w+1), B=(w+2,w+3) -> 16 LDG.128 in flight.
        float4 A[8], Bv[8];
        ldpair(w,     A);
        ldpair(w + 2, Bv);

        for (; w + 7 < whi; w += 4) {
            rmw(w,     sum4(A[0], A[1], A[2], A[3]));
            rmw(w + 1, sum4(A[4], A[5], A[6], A[7]));
            ldpair(w + 4, A);                     // refill A, depth stays 2
            rmw(w + 2, sum4(Bv[0], Bv[1], Bv[2], Bv[3]));
            rmw(w + 3, sum4(Bv[4], Bv[5], Bv[6], Bv[7]));
            ldpair(w + 6, Bv);                    // refill B
        }
        // Drain the two preloaded pairs (valid for w..w+3).
        rmw(w,     sum4(A[0], A[1], A[2], A[3]));
        rmw(w + 1, sum4(A[4], A[5], A[6], A[7]));
        rmw(w + 2, sum4(Bv[0], Bv[1], Bv[2], Bv[3]));
        rmw(w + 3, sum4(Bv[4], Bv[5], Bv[6], Bv[7]));
        w += 4;
    }
    // Tail: 0..3 leftover subwords.
    for (; w < whi; ++w) {
        const float* p = base + (size_t)w * DD;
        float4 e0 = *(const float4*)(p);
        float4 e1 = *(const float4*)(p + LSTRIDE);
        float4 e2 = *(const float4*)(p + 2 * LSTRIDE);
        float4 e3 = *(const float4*)(p + 3 * LSTRIDE);
        rmw(w, sum4(e0, e1, e2, e3));
    }

    // sent contribution (thread-owned columns, no barrier needed yet).
    {
        float4 cs = make_float4(0.f, 0.f, 0.f, 0.f);
        #pragma unroll
        for (int s = 0; s < TILE_S; ++s) {
            float4 v = ((const float4*)&tile_s[s][0])[tid];
            cs.x += v.x; cs.y += v.y; cs.z += v.z; cs.w += v.w;
        }
        const float k = 0.25f / (float)WW;
        float* sp = sent + b * DD + d0 + tid * 4;
        atomicAdd(sp + 0, cs.x * k);
        atomicAdd(sp + 1, cs.y * k);
        atomicAdd(sp + 2, cs.z * k);
        atomicAdd(sp + 3, cs.w * k);
    }

    __syncthreads();   // single cross-thread handoff: transpose below

    // Transposed coalesced write: word[b, d0+dd, s0 + ss4*4 .. +3] as float4.
    float* __restrict__ outb = word + ((size_t)b * DD + d0) * WW + s0;
    const int NOUT = (TILE_S / 4) * TILE_D;   // 3072 float4 stores
    for (int i2 = tid; i2 < NOUT; i2 += NTHR) {
        const int ss4 = i2 & 7;
        const int dd  = i2 >> 3;
        float4 v;
        v.x = 0.25f * tile_s[ss4 * 4 + 0][dd];
        v.y = 0.25f * tile_s[ss4 * 4 + 1][dd];
        v.z = 0.25f * tile_s[ss4 * 4 + 2][dd];
        v.w = 0.25f * tile_s[ss4 * 4 + 3][dd];
        *(float4*)(outb + (size_t)dd * WW + ss4 * 4) = v;
    }
}

extern "C" void kernel_launch(void* const* d_in, const int* in_sizes, int n_in,
                              void* d_out, int out_size) {
    const float* emb = (const float*)d_in[0];
    const int*   seg = (const int*)d_in[1];

    float* word = (float*)d_out;                   // [B, D, W]
    float* sent = word + (size_t)BB * DD * WW;     // [B, D]

    zero_sent_kernel<<<(BB * DD + 255) / 256, 256>>>(sent);

    dim3 grid(DD / TILE_D, WW / TILE_S, BB);       // (2, 16, 32) = 1024 blocks
    word_agg_kernel<<<grid, NTHR>>>(emb, seg, word, sent);
}